// round 3
// baseline (speedup 1.0000x reference)
#include <cuda_runtime.h>

#define N_NODES 100000
#define N_EDGES 1600000
#define N_DIR   (2 * N_EDGES)
#define DIM     64

// -------- scratch (device globals; no allocation allowed) --------
__device__ int   g_cnt[N_NODES];
__device__ int   g_off[N_NODES + 1];
__device__ int   g_cur[N_NODES];
__device__ float g_dis[N_NODES];
__device__ int   g_src[N_DIR];
__device__ float g_w[N_DIR];
__device__ float g_bufA[N_NODES * DIM];
__device__ float g_bufB[N_NODES * DIM];

// -------- 1. zero degree counters --------
__global__ void k_zero_cnt() {
    int i = blockIdx.x * blockDim.x + threadIdx.x;
    if (i < N_NODES) g_cnt[i] = 0;
}

// -------- 2. degree count (both endpoints: undirected doubling) --------
// NOTE: adj is int32 (JAX x64 disabled downcasts the declared int64).
__global__ void k_count(const int* __restrict__ adj) {
    int e = blockIdx.x * blockDim.x + threadIdx.x;
    if (e >= N_EDGES) return;
    int r = adj[e];
    int c = adj[N_EDGES + e];
    atomicAdd(&g_cnt[r], 1);
    atomicAdd(&g_cnt[c], 1);
}

// -------- 3. exclusive scan over counts (single block) + deg^-1/2 --------
__global__ void k_scan_dis() {
    __shared__ int wsum[32];
    __shared__ int carry_s;
    int tid  = threadIdx.x;
    int lane = tid & 31, wid = tid >> 5;
    if (tid == 0) carry_s = 0;
    __syncthreads();
    for (int base = 0; base < N_NODES; base += 1024) {
        int carry = carry_s;
        int i = base + tid;
        int v = (i < N_NODES) ? g_cnt[i] : 0;
        int incl = v;
        #pragma unroll
        for (int o = 1; o < 32; o <<= 1) {
            int t = __shfl_up_sync(0xffffffffu, incl, o);
            if (lane >= o) incl += t;
        }
        if (lane == 31) wsum[wid] = incl;
        __syncthreads();
        if (wid == 0) {
            int s = wsum[lane];
            #pragma unroll
            for (int o = 1; o < 32; o <<= 1) {
                int t = __shfl_up_sync(0xffffffffu, s, o);
                if (lane >= o) s += t;
            }
            wsum[lane] = s;
        }
        __syncthreads();
        int add = (wid > 0) ? wsum[wid - 1] : 0;
        incl += add + carry;
        int excl = incl - v;
        if (i < N_NODES) {
            g_off[i] = excl;
            g_cur[i] = excl;
            g_dis[i] = (v > 0) ? rsqrtf((float)v) : 0.0f;
        }
        __syncthreads();
        if (tid == 1023) carry_s = incl;
        __syncthreads();
    }
    if (tid == 0) g_off[N_NODES] = carry_s;
}

// -------- 4. place directed edges into CSR-by-dest, weight precomputed --------
__global__ void k_place(const int* __restrict__ adj) {
    int e = blockIdx.x * blockDim.x + threadIdx.x;
    if (e >= N_EDGES) return;
    int r = adj[e];
    int c = adj[N_EDGES + e];
    float w = g_dis[r] * g_dis[c];
    int p1 = atomicAdd(&g_cur[c], 1);
    g_src[p1] = r;
    g_w[p1]   = w;
    int p2 = atomicAdd(&g_cur[r], 1);
    g_src[p2] = c;
    g_w[p2]   = w;
}

// -------- 5. init accumulator: out = x0 --------
__global__ void k_copy(const float* __restrict__ x, float* __restrict__ out) {
    int i = blockIdx.x * blockDim.x + threadIdx.x;
    if (i < N_NODES * DIM) out[i] = x[i];
}

// -------- 6. SpMM layer: one warp per destination node --------
// xout = A_hat * xin; osum += xout; FINAL additionally scales by 1/4 and
// skips the (unused) xout store.
template <bool FINAL>
__global__ void __launch_bounds__(256)
k_spmm(const float* __restrict__ xin, float* __restrict__ xout,
       float* __restrict__ osum) {
    int warp_g = (blockIdx.x * blockDim.x + threadIdx.x) >> 5;
    int lane   = threadIdx.x & 31;
    if (warp_g >= N_NODES) return;
    int n   = warp_g;
    int beg = g_off[n];
    int end = g_off[n + 1];

    float2 acc = make_float2(0.0f, 0.0f);

    int base = beg;
    // full 32-edge chunks: each lane fetches one (src, w), broadcast via shfl
    for (; base + 32 <= end; base += 32) {
        int   s  = g_src[base + lane];
        float wt = g_w[base + lane];
        #pragma unroll
        for (int k = 0; k < 32; k++) {
            int   ss = __shfl_sync(0xffffffffu, s, k);
            float ww = __shfl_sync(0xffffffffu, wt, k);
            float2 v = __ldg(reinterpret_cast<const float2*>(xin + ss * DIM) + lane);
            acc.x = fmaf(ww, v.x, acc.x);
            acc.y = fmaf(ww, v.y, acc.y);
        }
    }
    // remainder
    int rem = end - base;
    if (rem > 0) {
        int   s  = 0;
        float wt = 0.0f;
        if (lane < rem) {
            s  = g_src[base + lane];
            wt = g_w[base + lane];
        }
        for (int k = 0; k < rem; k++) {
            int   ss = __shfl_sync(0xffffffffu, s, k);
            float ww = __shfl_sync(0xffffffffu, wt, k);
            float2 v = __ldg(reinterpret_cast<const float2*>(xin + ss * DIM) + lane);
            acc.x = fmaf(ww, v.x, acc.x);
            acc.y = fmaf(ww, v.y, acc.y);
        }
    }

    int o = n * DIM + lane * 2;
    float2* op   = reinterpret_cast<float2*>(osum + o);
    float2  prev = *op;
    if (FINAL) {
        prev.x = (prev.x + acc.x) * 0.25f;
        prev.y = (prev.y + acc.y) * 0.25f;
        *op = prev;
    } else {
        prev.x += acc.x;
        prev.y += acc.y;
        *op = prev;
        *reinterpret_cast<float2*>(xout + o) = acc;
    }
}

extern "C" void kernel_launch(void* const* d_in, const int* in_sizes, int n_in,
                              void* d_out, int out_size) {
    (void)in_sizes; (void)n_in; (void)out_size;
    const float* x   = (const float*)d_in[0];
    const int*   adj = (const int*)d_in[1];
    float*       out = (float*)d_out;

    void *pA = nullptr, *pB = nullptr;
    cudaGetSymbolAddress(&pA, g_bufA);
    cudaGetSymbolAddress(&pB, g_bufB);
    float* bufA = (float*)pA;
    float* bufB = (float*)pB;

    const int T = 256;
    k_zero_cnt<<<(N_NODES + T - 1) / T, T>>>();
    k_count<<<(N_EDGES + T - 1) / T, T>>>(adj);
    k_scan_dis<<<1, 1024>>>();
    k_place<<<(N_EDGES + T - 1) / T, T>>>(adj);
    k_copy<<<(N_NODES * DIM + T - 1) / T, T>>>(x, out);

    int spmm_blocks = (N_NODES * 32 + T - 1) / T;  // one warp per node
    k_spmm<false><<<spmm_blocks, T>>>(x,    bufA, out);   // layer 1
    k_spmm<false><<<spmm_blocks, T>>>(bufA, bufB, out);   // layer 2
    k_spmm<true ><<<spmm_blocks, T>>>(bufB, bufA, out);   // layer 3 + /4
}

// round 4
// speedup vs baseline: 1.0575x; 1.0575x over previous
#include <cuda_runtime.h>

#define N_NODES 100000
#define N_EDGES 1600000
#define N_DIR   (2 * N_EDGES)
#define DIM     64

// -------- scratch (device globals; no allocation allowed) --------
__device__ int   g_cnt[N_NODES];
__device__ int   g_off[N_NODES + 1];
__device__ int   g_cur[N_NODES];
__device__ float g_dis[N_NODES];
__device__ int   g_src[N_DIR];
__device__ float g_bufA[N_NODES * DIM];   // z (dis-scaled features), ping
__device__ float g_bufB[N_NODES * DIM];   // z, pong

// -------- 1. zero degree counters --------
__global__ void k_zero_cnt() {
    int i = blockIdx.x * blockDim.x + threadIdx.x;
    if (i < N_NODES) g_cnt[i] = 0;
}

// -------- 2. degree count: 4 undirected edges per thread, int4 reads --------
__global__ void k_count(const int* __restrict__ adj) {
    int t = blockIdx.x * blockDim.x + threadIdx.x;
    int e4 = t * 4;
    if (e4 >= N_EDGES) return;
    int4 r = *reinterpret_cast<const int4*>(adj + e4);
    int4 c = *reinterpret_cast<const int4*>(adj + N_EDGES + e4);
    atomicAdd(&g_cnt[r.x], 1); atomicAdd(&g_cnt[c.x], 1);
    atomicAdd(&g_cnt[r.y], 1); atomicAdd(&g_cnt[c.y], 1);
    atomicAdd(&g_cnt[r.z], 1); atomicAdd(&g_cnt[c.z], 1);
    atomicAdd(&g_cnt[r.w], 1); atomicAdd(&g_cnt[c.w], 1);
}

// -------- 3. exclusive scan over counts (single block) + deg^-1/2 --------
__global__ void k_scan_dis() {
    __shared__ int wsum[32];
    __shared__ int carry_s;
    int tid  = threadIdx.x;
    int lane = tid & 31, wid = tid >> 5;
    if (tid == 0) carry_s = 0;
    __syncthreads();
    for (int base = 0; base < N_NODES; base += 1024) {
        int carry = carry_s;
        int i = base + tid;
        int v = (i < N_NODES) ? g_cnt[i] : 0;
        int incl = v;
        #pragma unroll
        for (int o = 1; o < 32; o <<= 1) {
            int t = __shfl_up_sync(0xffffffffu, incl, o);
            if (lane >= o) incl += t;
        }
        if (lane == 31) wsum[wid] = incl;
        __syncthreads();
        if (wid == 0) {
            int s = wsum[lane];
            #pragma unroll
            for (int o = 1; o < 32; o <<= 1) {
                int t = __shfl_up_sync(0xffffffffu, s, o);
                if (lane >= o) s += t;
            }
            wsum[lane] = s;
        }
        __syncthreads();
        int add = (wid > 0) ? wsum[wid - 1] : 0;
        incl += add + carry;
        int excl = incl - v;
        if (i < N_NODES) {
            g_off[i] = excl;
            g_cur[i] = excl;
            g_dis[i] = (v > 0) ? rsqrtf((float)v) : 0.0f;
        }
        __syncthreads();
        if (tid == 1023) carry_s = incl;
        __syncthreads();
    }
    if (tid == 0) g_off[N_NODES] = carry_s;
}

// -------- 4. place directed edges into CSR-by-dest (index only, no weight) --
// 4 undirected edges per thread -> 8 independent atomic->store chains (MLP).
__global__ void k_place(const int* __restrict__ adj) {
    int t = blockIdx.x * blockDim.x + threadIdx.x;
    int e4 = t * 4;
    if (e4 >= N_EDGES) return;
    int4 r = *reinterpret_cast<const int4*>(adj + e4);
    int4 c = *reinterpret_cast<const int4*>(adj + N_EDGES + e4);
    int p0 = atomicAdd(&g_cur[c.x], 1);
    int p1 = atomicAdd(&g_cur[r.x], 1);
    int p2 = atomicAdd(&g_cur[c.y], 1);
    int p3 = atomicAdd(&g_cur[r.y], 1);
    int p4 = atomicAdd(&g_cur[c.z], 1);
    int p5 = atomicAdd(&g_cur[r.z], 1);
    int p6 = atomicAdd(&g_cur[c.w], 1);
    int p7 = atomicAdd(&g_cur[r.w], 1);
    g_src[p0] = r.x;  g_src[p1] = c.x;
    g_src[p2] = r.y;  g_src[p3] = c.y;
    g_src[p4] = r.z;  g_src[p5] = c.z;
    g_src[p6] = r.w;  g_src[p7] = c.w;
}

// -------- 5. init: out = x, z0 = dis .* x --------
__global__ void k_init(const float* __restrict__ x, float* __restrict__ out,
                       float* __restrict__ z) {
    int i = blockIdx.x * blockDim.x + threadIdx.x;   // float2 index
    if (i >= N_NODES * DIM / 2) return;
    float2 v = reinterpret_cast<const float2*>(x)[i];
    float  d = g_dis[i / (DIM / 2)];
    reinterpret_cast<float2*>(out)[i] = v;
    float2 zv; zv.x = v.x * d; zv.y = v.y * d;
    reinterpret_cast<float2*>(z)[i] = zv;
}

// -------- 6. SpMM layer: one warp per destination node, unweighted sum -----
// s = sum_{neighbors} z_in[src];  osum += dis[n]*s  (FINAL: *(1/4));
// z_out = dis[n]^2 * s  (skipped when FINAL).
template <bool FINAL>
__global__ void __launch_bounds__(256)
k_spmm(const float* __restrict__ zin, float* __restrict__ zout,
       float* __restrict__ osum) {
    int warp_g = (blockIdx.x * blockDim.x + threadIdx.x) >> 5;
    int lane   = threadIdx.x & 31;
    if (warp_g >= N_NODES) return;
    int n   = warp_g;
    int beg = __ldg(&g_off[n]);
    int end = __ldg(&g_off[n + 1]);

    float2 acc = make_float2(0.0f, 0.0f);

    int base = beg;
    for (; base + 32 <= end; base += 32) {
        int s = __ldg(&g_src[base + lane]);
        #pragma unroll
        for (int k = 0; k < 32; k++) {
            int ss = __shfl_sync(0xffffffffu, s, k);
            float2 v = __ldg(reinterpret_cast<const float2*>(zin + ss * DIM) + lane);
            acc.x += v.x;
            acc.y += v.y;
        }
    }
    int rem = end - base;
    if (rem > 0) {
        int s = (lane < rem) ? __ldg(&g_src[base + lane]) : 0;
        for (int k = 0; k < rem; k++) {
            int ss = __shfl_sync(0xffffffffu, s, k);
            float2 v = __ldg(reinterpret_cast<const float2*>(zin + ss * DIM) + lane);
            acc.x += v.x;
            acc.y += v.y;
        }
    }

    float d = __ldg(&g_dis[n]);
    int o = n * DIM + lane * 2;
    float2* op   = reinterpret_cast<float2*>(osum + o);
    float2  prev = *op;
    if (FINAL) {
        prev.x = (prev.x + d * acc.x) * 0.25f;
        prev.y = (prev.y + d * acc.y) * 0.25f;
        *op = prev;
    } else {
        prev.x += d * acc.x;
        prev.y += d * acc.y;
        *op = prev;
        float d2 = d * d;
        float2 zv; zv.x = d2 * acc.x; zv.y = d2 * acc.y;
        *reinterpret_cast<float2*>(zout + o) = zv;
    }
}

extern "C" void kernel_launch(void* const* d_in, const int* in_sizes, int n_in,
                              void* d_out, int out_size) {
    (void)in_sizes; (void)n_in; (void)out_size;
    const float* x   = (const float*)d_in[0];
    const int*   adj = (const int*)d_in[1];
    float*       out = (float*)d_out;

    void *pA = nullptr, *pB = nullptr;
    cudaGetSymbolAddress(&pA, g_bufA);
    cudaGetSymbolAddress(&pB, g_bufB);
    float* bufA = (float*)pA;
    float* bufB = (float*)pB;

    const int T = 256;
    k_zero_cnt<<<(N_NODES + T - 1) / T, T>>>();
    k_count<<<(N_EDGES / 4 + T - 1) / T, T>>>(adj);
    k_scan_dis<<<1, 1024>>>();
    k_place<<<(N_EDGES / 4 + T - 1) / T, T>>>(adj);
    k_init<<<(N_NODES * DIM / 2 + T - 1) / T, T>>>(x, out, bufA);

    int spmm_blocks = (N_NODES * 32 + T - 1) / T;  // one warp per node
    k_spmm<false><<<spmm_blocks, T>>>(bufA, bufB, out);   // layer 1
    k_spmm<false><<<spmm_blocks, T>>>(bufB, bufA, out);   // layer 2
    k_spmm<true ><<<spmm_blocks, T>>>(bufA, bufB, out);   // layer 3 + /4
}

// round 5
// speedup vs baseline: 1.4677x; 1.3879x over previous
#include <cuda_runtime.h>
#include <cuda_fp16.h>

#define N_NODES 100000
#define N_EDGES 1600000
#define N_DIR   (2 * N_EDGES)
#define DIM     64
#define NB_SCAN 98            // ceil(100000 / 1024)

// -------- scratch (device globals; no allocation allowed) --------
__device__ int    g_cnt[N_NODES];
__device__ int    g_off[N_NODES + 1];
__device__ int    g_cur[N_NODES];
__device__ float  g_dis[N_NODES];
__device__ int    g_src[N_DIR];
__device__ int    g_bsum[NB_SCAN];
__device__ int    g_bbase[NB_SCAN];
__device__ __half g_zA[N_NODES * DIM];   // dis-scaled features, fp16, ping
__device__ __half g_zB[N_NODES * DIM];   // pong

// -------- 1. zero degree counters (vectorized) --------
__global__ void k_zero_cnt() {
    int i4 = blockIdx.x * blockDim.x + threadIdx.x;
    if (i4 < N_NODES / 4)
        reinterpret_cast<int4*>(g_cnt)[i4] = make_int4(0, 0, 0, 0);
}

// -------- 2. degree count: 8 undirected edges per thread --------
__global__ void k_count(const int* __restrict__ adj) {
    int t = blockIdx.x * blockDim.x + threadIdx.x;
    int e8 = t * 8;
    if (e8 >= N_EDGES) return;
    int4 r0 = *reinterpret_cast<const int4*>(adj + e8);
    int4 r1 = *reinterpret_cast<const int4*>(adj + e8 + 4);
    int4 c0 = *reinterpret_cast<const int4*>(adj + N_EDGES + e8);
    int4 c1 = *reinterpret_cast<const int4*>(adj + N_EDGES + e8 + 4);
    atomicAdd(&g_cnt[r0.x], 1); atomicAdd(&g_cnt[c0.x], 1);
    atomicAdd(&g_cnt[r0.y], 1); atomicAdd(&g_cnt[c0.y], 1);
    atomicAdd(&g_cnt[r0.z], 1); atomicAdd(&g_cnt[c0.z], 1);
    atomicAdd(&g_cnt[r0.w], 1); atomicAdd(&g_cnt[c0.w], 1);
    atomicAdd(&g_cnt[r1.x], 1); atomicAdd(&g_cnt[c1.x], 1);
    atomicAdd(&g_cnt[r1.y], 1); atomicAdd(&g_cnt[c1.y], 1);
    atomicAdd(&g_cnt[r1.z], 1); atomicAdd(&g_cnt[c1.z], 1);
    atomicAdd(&g_cnt[r1.w], 1); atomicAdd(&g_cnt[c1.w], 1);
}

// -------- 3a. per-block sums of g_cnt (1024 nodes / block) --------
__global__ void k_scan1() {
    int b = blockIdx.x, t = threadIdx.x;
    int lane = t & 31, wid = t >> 5;
    int i4 = b * 256 + t;
    int4 v = (i4 * 4 < N_NODES) ? reinterpret_cast<const int4*>(g_cnt)[i4]
                                : make_int4(0, 0, 0, 0);
    int s = v.x + v.y + v.z + v.w;
    #pragma unroll
    for (int o = 16; o > 0; o >>= 1) s += __shfl_down_sync(0xffffffffu, s, o);
    __shared__ int ws[8];
    if (lane == 0) ws[wid] = s;
    __syncthreads();
    if (wid == 0) {
        int x = (lane < 8) ? ws[lane] : 0;
        #pragma unroll
        for (int o = 4; o > 0; o >>= 1) x += __shfl_down_sync(0xffffffffu, x, o);
        if (lane == 0) g_bsum[b] = x;
    }
}

// -------- 3b. exclusive scan of the NB_SCAN block sums --------
__global__ void k_scan2() {
    int t = threadIdx.x;           // 128 threads
    int lane = t & 31, wid = t >> 5;
    int v = (t < NB_SCAN) ? g_bsum[t] : 0;
    int incl = v;
    #pragma unroll
    for (int o = 1; o < 32; o <<= 1) {
        int x = __shfl_up_sync(0xffffffffu, incl, o);
        if (lane >= o) incl += x;
    }
    __shared__ int ws[4];
    if (lane == 31) ws[wid] = incl;
    __syncthreads();
    if (wid == 0 && lane < 4) {
        int s = ws[lane];
        #pragma unroll
        for (int o = 1; o < 4; o <<= 1) {
            int x = __shfl_up_sync(0x0000000fu, s, o);
            if (lane >= o) s += x;
        }
        ws[lane] = s;
    }
    __syncthreads();
    int excl = incl - v + ((wid > 0) ? ws[wid - 1] : 0);
    if (t < NB_SCAN) g_bbase[t] = excl;
}

// -------- 3c. block-local scan + base; emit g_off / g_cur / g_dis --------
__global__ void k_scan3() {
    int b = blockIdx.x, t = threadIdx.x;
    int lane = t & 31, wid = t >> 5;
    int i4 = b * 256 + t;
    bool ok = (i4 * 4 < N_NODES);
    int4 v = ok ? reinterpret_cast<const int4*>(g_cnt)[i4] : make_int4(0, 0, 0, 0);
    int tsum = v.x + v.y + v.z + v.w;
    int incl = tsum;
    #pragma unroll
    for (int o = 1; o < 32; o <<= 1) {
        int x = __shfl_up_sync(0xffffffffu, incl, o);
        if (lane >= o) incl += x;
    }
    __shared__ int ws[8];
    if (lane == 31) ws[wid] = incl;
    __syncthreads();
    if (wid == 0 && lane < 8) {
        int s = ws[lane];
        #pragma unroll
        for (int o = 1; o < 8; o <<= 1) {
            int x = __shfl_up_sync(0x000000ffu, s, o);
            if (lane >= o) s += x;
        }
        ws[lane] = s;
    }
    __syncthreads();
    int base = g_bbase[b] + (incl - tsum) + ((wid > 0) ? ws[wid - 1] : 0);
    if (ok) {
        int o0 = base, o1 = o0 + v.x, o2 = o1 + v.y, o3 = o2 + v.z;
        int4 off = make_int4(o0, o1, o2, o3);
        reinterpret_cast<int4*>(g_off)[i4] = off;
        reinterpret_cast<int4*>(g_cur)[i4] = off;
        float4 dd;
        dd.x = (v.x > 0) ? rsqrtf((float)v.x) : 0.0f;
        dd.y = (v.y > 0) ? rsqrtf((float)v.y) : 0.0f;
        dd.z = (v.z > 0) ? rsqrtf((float)v.z) : 0.0f;
        dd.w = (v.w > 0) ? rsqrtf((float)v.w) : 0.0f;
        reinterpret_cast<float4*>(g_dis)[i4] = dd;
    }
    if (b == 0 && t == 0) g_off[N_NODES] = N_DIR;
}

// -------- 4. place directed edges into CSR-by-dest (index only) --------
// 8 undirected edges per thread -> 16 independent atomic->store chains.
__global__ void k_place(const int* __restrict__ adj) {
    int t = blockIdx.x * blockDim.x + threadIdx.x;
    int e8 = t * 8;
    if (e8 >= N_EDGES) return;
    int4 r0 = *reinterpret_cast<const int4*>(adj + e8);
    int4 r1 = *reinterpret_cast<const int4*>(adj + e8 + 4);
    int4 c0 = *reinterpret_cast<const int4*>(adj + N_EDGES + e8);
    int4 c1 = *reinterpret_cast<const int4*>(adj + N_EDGES + e8 + 4);
    int p0  = atomicAdd(&g_cur[c0.x], 1);
    int p1  = atomicAdd(&g_cur[r0.x], 1);
    int p2  = atomicAdd(&g_cur[c0.y], 1);
    int p3  = atomicAdd(&g_cur[r0.y], 1);
    int p4  = atomicAdd(&g_cur[c0.z], 1);
    int p5  = atomicAdd(&g_cur[r0.z], 1);
    int p6  = atomicAdd(&g_cur[c0.w], 1);
    int p7  = atomicAdd(&g_cur[r0.w], 1);
    int p8  = atomicAdd(&g_cur[c1.x], 1);
    int p9  = atomicAdd(&g_cur[r1.x], 1);
    int p10 = atomicAdd(&g_cur[c1.y], 1);
    int p11 = atomicAdd(&g_cur[r1.y], 1);
    int p12 = atomicAdd(&g_cur[c1.z], 1);
    int p13 = atomicAdd(&g_cur[r1.z], 1);
    int p14 = atomicAdd(&g_cur[c1.w], 1);
    int p15 = atomicAdd(&g_cur[r1.w], 1);
    g_src[p0]  = r0.x;  g_src[p1]  = c0.x;
    g_src[p2]  = r0.y;  g_src[p3]  = c0.y;
    g_src[p4]  = r0.z;  g_src[p5]  = c0.z;
    g_src[p6]  = r0.w;  g_src[p7]  = c0.w;
    g_src[p8]  = r1.x;  g_src[p9]  = c1.x;
    g_src[p10] = r1.y;  g_src[p11] = c1.y;
    g_src[p12] = r1.z;  g_src[p13] = c1.z;
    g_src[p14] = r1.w;  g_src[p15] = c1.w;
}

// -------- 5. init: out = x, z0 = half(dis .* x) --------
__global__ void k_init(const float* __restrict__ x, float* __restrict__ out,
                       __half2* __restrict__ z) {
    int i = blockIdx.x * blockDim.x + threadIdx.x;   // float2 / half2 index
    if (i >= N_NODES * DIM / 2) return;
    float2 v = reinterpret_cast<const float2*>(x)[i];
    float  d = __ldg(&g_dis[i >> 5]);
    reinterpret_cast<float2*>(out)[i] = v;
    z[i] = __floats2half2_rn(v.x * d, v.y * d);
}

// -------- 6. SpMM layer: one warp per destination node --------
// acc = sum_{neighbors} z_in[src] (fp32 acc of fp16 rows);
// osum += dis[n]*acc (FINAL: *1/4); z_out = half(dis[n]^2 * acc).
template <bool FINAL>
__global__ void __launch_bounds__(256)
k_spmm(const __half2* __restrict__ zin, __half2* __restrict__ zout,
       float* __restrict__ osum) {
    int warp_g = (blockIdx.x * blockDim.x + threadIdx.x) >> 5;
    int lane   = threadIdx.x & 31;
    if (warp_g >= N_NODES) return;
    int n   = warp_g;
    int beg = __ldg(&g_off[n]);
    int end = __ldg(&g_off[n + 1]);

    float2 acc = make_float2(0.0f, 0.0f);

    int base = beg;
    for (; base + 32 <= end; base += 32) {
        int s = __ldg(&g_src[base + lane]);
        #pragma unroll
        for (int k = 0; k < 32; k++) {
            int ss = __shfl_sync(0xffffffffu, s, k);
            float2 v = __half22float2(__ldg(zin + ss * 32 + lane));
            acc.x += v.x;
            acc.y += v.y;
        }
    }
    int rem = end - base;
    if (rem > 0) {
        int s = (lane < rem) ? __ldg(&g_src[base + lane]) : 0;
        for (int k = 0; k < rem; k++) {
            int ss = __shfl_sync(0xffffffffu, s, k);
            float2 v = __half22float2(__ldg(zin + ss * 32 + lane));
            acc.x += v.x;
            acc.y += v.y;
        }
    }

    float d = __ldg(&g_dis[n]);
    int o = n * 32 + lane;                     // float2 / half2 index
    float2* op   = reinterpret_cast<float2*>(osum) + o;
    float2  prev = *op;
    if (FINAL) {
        prev.x = (prev.x + d * acc.x) * 0.25f;
        prev.y = (prev.y + d * acc.y) * 0.25f;
        *op = prev;
    } else {
        prev.x += d * acc.x;
        prev.y += d * acc.y;
        *op = prev;
        float d2 = d * d;
        zout[o] = __floats2half2_rn(d2 * acc.x, d2 * acc.y);
    }
}

extern "C" void kernel_launch(void* const* d_in, const int* in_sizes, int n_in,
                              void* d_out, int out_size) {
    (void)in_sizes; (void)n_in; (void)out_size;
    const float* x   = (const float*)d_in[0];
    const int*   adj = (const int*)d_in[1];
    float*       out = (float*)d_out;

    void *pA = nullptr, *pB = nullptr;
    cudaGetSymbolAddress(&pA, g_zA);
    cudaGetSymbolAddress(&pB, g_zB);
    __half2* zA = (__half2*)pA;
    __half2* zB = (__half2*)pB;

    const int T = 256;
    k_zero_cnt<<<(N_NODES / 4 + T - 1) / T, T>>>();
    k_count<<<(N_EDGES / 8 + T - 1) / T, T>>>(adj);
    k_scan1<<<NB_SCAN, 256>>>();
    k_scan2<<<1, 128>>>();
    k_scan3<<<NB_SCAN, 256>>>();
    k_place<<<(N_EDGES / 8 + T - 1) / T, T>>>(adj);
    k_init<<<(N_NODES * DIM / 2 + T - 1) / T, T>>>(x, out, zA);

    int spmm_blocks = (N_NODES * 32 + T - 1) / T;  // one warp per node
    k_spmm<false><<<spmm_blocks, T>>>(zA, zB, out);   // layer 1
    k_spmm<false><<<spmm_blocks, T>>>(zB, zA, out);   // layer 2
    k_spmm<true ><<<spmm_blocks, T>>>(zA, zB, out);   // layer 3 + /4
}